// round 15
// baseline (speedup 1.0000x reference)
#include <cuda_runtime.h>
#include <cuda_bf16.h>
#include <cuda_fp16.h>
#include <cuda_fp8.h>
#include <cstdint>
#include <math.h>

// ---------------- problem constants ----------------
#define BSZ   2
#define LQ    17821
#define CDIM  256
#define MTOK  (BSZ*LQ)          // 35642
#define MPAD  35712             // 279 * 128
#define MT128 279
#define DFFN  1024
#define PAD   72                // smem row stride in halves (144B, conflict-free)
#define PAD2  (PAD*2)

__device__ __constant__ int c_H[4]  = {100, 50, 25, 13};
__device__ __constant__ int c_W[4]  = {134, 67, 34, 17};
__device__ __constant__ int c_st[4] = {0, 13400, 16750, 17600};

// ---------------- scratch (no allocs; zero-initialized .bss) ----------------
__device__ __nv_bfloat16 g_nb    [(size_t)MPAD*CDIM];
__device__ __nv_bfloat16 g_qb    [(size_t)MPAD*CDIM];
__device__ unsigned char g_value8[(size_t)MPAD*CDIM];   // fp8 e4m3 value tensor
__device__ __half        g_off   [(size_t)MTOK*CDIM];
__device__ __half        g_awl   [(size_t)MTOK*128];
__device__ __nv_bfloat16 g_attnb [(size_t)MPAD*CDIM];
__device__ float         g_x     [(size_t)MTOK*CDIM];
__device__ __nv_bfloat16 g_n2b   [(size_t)MPAD*CDIM];
__device__ __nv_bfloat16 g_hb    [(size_t)MPAD*DFFN];
// converted weights: Wv,Woff,Waw,Wo,W1,W2,W3
#define WOFF_WV   0
#define WOFF_WOFF 65536
#define WOFF_WAW  131072
#define WOFF_WO   163840
#define WOFF_W1   229376
#define WOFF_W2   491520
#define WOFF_W3   753664
__device__ __nv_bfloat16 g_wb[1015808];

// ================= helpers =================
__device__ __forceinline__ uint32_t smem_u32(const void* p) {
    uint32_t a;
    asm("{ .reg .u64 t; cvta.to.shared.u64 t, %1; cvt.u32.u64 %0, t; }" : "=r"(a) : "l"(p));
    return a;
}
__device__ __forceinline__ void ldsm4(uint32_t* r, uint32_t addr) {
    asm volatile("ldmatrix.sync.aligned.m8n8.x4.shared.b16 {%0,%1,%2,%3}, [%4];"
        : "=r"(r[0]), "=r"(r[1]), "=r"(r[2]), "=r"(r[3]) : "r"(addr));
}
__device__ __forceinline__ void mma_bf16(float* c, const uint32_t* a, const uint32_t* b) {
    asm volatile(
        "mma.sync.aligned.m16n8k16.row.col.f32.bf16.bf16.f32 "
        "{%0,%1,%2,%3}, {%4,%5,%6,%7}, {%8,%9}, {%0,%1,%2,%3};"
        : "+f"(c[0]), "+f"(c[1]), "+f"(c[2]), "+f"(c[3])
        : "r"(a[0]), "r"(a[1]), "r"(a[2]), "r"(a[3]), "r"(b[0]), "r"(b[1]));
}
__device__ __forceinline__ void cp16(uint32_t dst, const void* src) {
    asm volatile("cp.async.ca.shared.global [%0], [%1], 16;" :: "r"(dst), "l"(src));
}
#define CP_COMMIT() asm volatile("cp.async.commit_group;" ::: "memory")
#define CP_WAIT1()  asm volatile("cp.async.wait_group 1;" ::: "memory")
#define CP_WAIT0()  asm volatile("cp.async.wait_group 0;" ::: "memory")

__device__ __forceinline__ __half2 fp8x2_to_h2(unsigned short s) {
    __half2_raw r = __nv_cvt_fp8x2_to_halfraw2((__nv_fp8x2_storage_t)s, __NV_E4M3);
    return *(__half2*)&r;
}
__device__ __forceinline__ void acc8(__half2* acch, uint4 v, __half2 wh) {
    acch[0] = __hfma2(fp8x2_to_h2(v.x & 0xFFFFu), wh, acch[0]);
    acch[1] = __hfma2(fp8x2_to_h2(v.x >> 16),     wh, acch[1]);
    acch[2] = __hfma2(fp8x2_to_h2(v.y & 0xFFFFu), wh, acch[2]);
    acch[3] = __hfma2(fp8x2_to_h2(v.y >> 16),     wh, acch[3]);
    acch[4] = __hfma2(fp8x2_to_h2(v.z & 0xFFFFu), wh, acch[4]);
    acch[5] = __hfma2(fp8x2_to_h2(v.z >> 16),     wh, acch[5]);
    acch[6] = __hfma2(fp8x2_to_h2(v.w & 0xFFFFu), wh, acch[6]);
    acch[7] = __hfma2(fp8x2_to_h2(v.w >> 16),     wh, acch[7]);
}

// ---------------- weight fp32 -> bf16 convert ----------------
struct WSrc { const float* s[7]; };
__device__ __constant__ int c_wsz [7] = {65536, 65536, 32768, 65536, 262144, 262144, 262144};
__device__ __constant__ int c_woff[7] = {WOFF_WV, WOFF_WOFF, WOFF_WAW, WOFF_WO, WOFF_W1, WOFF_W2, WOFF_W3};

__global__ void __launch_bounds__(256) wconv_kernel(WSrc w) {
    int seg = blockIdx.y;
    int i = (blockIdx.x * 256 + threadIdx.x) * 4;
    if (i >= c_wsz[seg]) return;
    float4 v = *(const float4*)(w.s[seg] + i);
    __nv_bfloat16* d = g_wb + c_woff[seg] + i;
    *(__nv_bfloat162*)(d)     = __floats2bfloat162_rn(v.x, v.y);
    *(__nv_bfloat162*)(d + 2) = __floats2bfloat162_rn(v.z, v.w);
}

// ---------------- RMSNorm -> bf16 (+ optional bf16 normed+addend) ----------------
__global__ void __launch_bounds__(256) rmsnorm_kernel(
    const float* __restrict__ x, const float* __restrict__ w,
    __nv_bfloat16* __restrict__ out, const float* __restrict__ addend,
    __nv_bfloat16* __restrict__ out2)
{
    int row  = blockIdx.x * 8 + (threadIdx.x >> 5);
    if (row >= MTOK) return;
    int lane = threadIdx.x & 31;
    const float4* xr = (const float4*)(x + (size_t)row * CDIM);
    float4 v0 = xr[lane];
    float4 v1 = xr[lane + 32];
    float ss = v0.x*v0.x + v0.y*v0.y + v0.z*v0.z + v0.w*v0.w
             + v1.x*v1.x + v1.y*v1.y + v1.z*v1.z + v1.w*v1.w;
    #pragma unroll
    for (int o = 16; o > 0; o >>= 1) ss += __shfl_xor_sync(0xffffffffu, ss, o);
    float s = rsqrtf(ss * (1.0f / CDIM) + 1e-6f);
    const float4* w4 = (const float4*)w;
    float4 g0 = w4[lane], g1 = w4[lane + 32];
    float n0x = v0.x*s*g0.x, n0y = v0.y*s*g0.y, n0z = v0.z*s*g0.z, n0w = v0.w*s*g0.w;
    float n1x = v1.x*s*g1.x, n1y = v1.y*s*g1.y, n1z = v1.z*s*g1.z, n1w = v1.w*s*g1.w;
    __nv_bfloat162* o2 = (__nv_bfloat162*)(out + (size_t)row * CDIM);
    o2[lane*2+0]  = __floats2bfloat162_rn(n0x, n0y);
    o2[lane*2+1]  = __floats2bfloat162_rn(n0z, n0w);
    o2[64+lane*2] = __floats2bfloat162_rn(n1x, n1y);
    o2[65+lane*2] = __floats2bfloat162_rn(n1z, n1w);
    if (out2) {
        const float4* a4 = (const float4*)(addend + (size_t)row * CDIM);
        float4 p0 = a4[lane], p1 = a4[lane + 32];
        __nv_bfloat162* q2 = (__nv_bfloat162*)(out2 + (size_t)row * CDIM);
        q2[lane*2+0]  = __floats2bfloat162_rn(n0x + p0.x, n0y + p0.y);
        q2[lane*2+1]  = __floats2bfloat162_rn(n0z + p0.z, n0w + p0.w);
        q2[64+lane*2] = __floats2bfloat162_rn(n1x + p1.x, n1y + p1.y);
        q2[65+lane*2] = __floats2bfloat162_rn(n1z + p1.z, n1w + p1.w);
    }
}

// ---------------- HMMA GEMM, 3-stage cp.async ring (R10 config) ----------------
#define TILE_BYTES  (128 * PAD * 2)     // 18432
#define STAGE_BYTES (2 * TILE_BYTES)    // 36864: [As | Bs]
#define NSTAGE 3

__global__ void __launch_bounds__(256) hmma_gemm_kernel(
    const __nv_bfloat16* __restrict__ A, const __nv_bfloat16* __restrict__ B,
    const float* __restrict__ bias, const float* __restrict__ bias2,
    float* __restrict__ outp, float* __restrict__ outp2,
    unsigned char* __restrict__ out8,
    int M, int N, int N1, int K,
    const float* __restrict__ residual, const float* __restrict__ gain)
{
    extern __shared__ __align__(16) char smem[];
    uint32_t sb = smem_u32(smem);
    int tid = threadIdx.x, lane = tid & 31, wid = tid >> 5;
    int m0 = blockIdx.y * 128, n0 = blockIdx.x * 128;
    int warp_m = (wid & 1) * 64, warp_n = (wid >> 1) * 32;

    float acc[4][4][4] = {};

    int sub = lane >> 3, lrow = lane & 7;
    uint32_t a_off = ((warp_m + (sub & 1) * 8 + lrow) * PAD + (sub >> 1) * 8) * 2;
    uint32_t b_off = TILE_BYTES + ((warp_n + (sub >> 1) * 8 + lrow) * PAD + (sub & 1) * 8) * 2;

    const int NCH = K >> 6;
    const int ld4 = K >> 3;
    int lrow4 = tid >> 3, lcol4 = tid & 7;
    const uint4* agl = (const uint4*)(A + (size_t)m0 * K) + (size_t)lrow4 * ld4 + lcol4;
    const uint4* bgl = (const uint4*)(B + (size_t)n0 * K) + (size_t)lrow4 * ld4 + lcol4;
    uint32_t sdst = sb + lrow4 * (PAD * 2) + lcol4 * 16;

    #pragma unroll
    for (int s = 0; s < 2; s++) {
        if (s < NCH) {
            uint32_t d = sdst + s * STAGE_BYTES;
            const uint4* ag = agl + (size_t)s * 8;
            const uint4* bg = bgl + (size_t)s * 8;
            #pragma unroll
            for (int p = 0; p < 4; p++) {
                cp16(d + p * 32 * (PAD * 2),              ag + (size_t)p * 32 * ld4);
                cp16(d + TILE_BYTES + p * 32 * (PAD * 2), bg + (size_t)p * 32 * ld4);
            }
        }
        CP_COMMIT();
    }

    int stage = 0, lstage = 2;
    for (int c = 0; c < NCH; c++) {
        if (c + 1 < NCH) CP_WAIT1(); else CP_WAIT0();
        __syncthreads();
        if (c + 2 < NCH) {
            uint32_t d = sdst + lstage * STAGE_BYTES;
            const uint4* ag = agl + (size_t)(c + 2) * 8;
            const uint4* bg = bgl + (size_t)(c + 2) * 8;
            #pragma unroll
            for (int p = 0; p < 4; p++) {
                cp16(d + p * 32 * (PAD * 2),              ag + (size_t)p * 32 * ld4);
                cp16(d + TILE_BYTES + p * 32 * (PAD * 2), bg + (size_t)p * 32 * ld4);
            }
            CP_COMMIT();
            if (++lstage == NSTAGE) lstage = 0;
        }
        uint32_t ab = sb + stage * STAGE_BYTES + a_off;
        uint32_t bb = sb + stage * STAGE_BYTES + b_off;
        #pragma unroll
        for (int ks = 0; ks < 4; ks++) {
            uint32_t af[4][4], bf[2][4];
            #pragma unroll
            for (int mt = 0; mt < 4; mt++) ldsm4(af[mt], ab + (mt * 16 * PAD + ks * 16) * 2);
            #pragma unroll
            for (int pr = 0; pr < 2; pr++) ldsm4(bf[pr], bb + (pr * 16 * PAD + ks * 16) * 2);
            #pragma unroll
            for (int mt = 0; mt < 4; mt++) {
                mma_bf16(acc[mt][0], af[mt], &bf[0][0]);
                mma_bf16(acc[mt][1], af[mt], &bf[0][2]);
                mma_bf16(acc[mt][2], af[mt], &bf[1][0]);
                mma_bf16(acc[mt][3], af[mt], &bf[1][2]);
            }
        }
        if (++stage == NSTAGE) stage = 0;
    }

    int crow = lane >> 2, ccol = (lane & 3) * 2;
    #pragma unroll
    for (int mt = 0; mt < 4; mt++) {
        #pragma unroll
        for (int half = 0; half < 2; half++) {
            int m = m0 + warp_m + mt * 16 + crow + half * 8;
            if (m >= M) continue;
            #pragma unroll
            for (int nt = 0; nt < 4; nt++) {
                int n = n0 + warp_n + nt * 8 + ccol;
                float vx = acc[mt][nt][half * 2 + 0];
                float vy = acc[mt][nt][half * 2 + 1];
                if (outp2) {
                    if (n < N1) {
                        __half2 hv = __floats2half2_rn(vx + bias[n], vy + bias[n + 1]);
                        *(__half2*)((__half*)outp + (size_t)m * N1 + n) = hv;
                    } else {
                        int S2 = N - N1, n2 = n - N1;
                        __half2 hv = __floats2half2_rn(vx + bias2[n2], vy + bias2[n2 + 1]);
                        *(__half2*)((__half*)outp2 + (size_t)m * S2 + n2) = hv;
                    }
                } else {
                    vx += bias[n]; vy += bias[n + 1];
                    if (residual) {
                        float2 rr = *(const float2*)(residual + (size_t)m * N1 + n);
                        vx = rr.x + gain[n]     * vx;
                        vy = rr.y + gain[n + 1] * vy;
                    }
                    if (out8) {
                        *(unsigned short*)(out8 + (size_t)m * N1 + n) =
                            (unsigned short)__nv_cvt_float2_to_fp8x2(
                                make_float2(vx, vy), __NV_SATFINITE, __NV_E4M3);
                    } else {
                        *(float2*)(outp + (size_t)m * N1 + n) = make_float2(vx, vy);
                    }
                }
            }
        }
    }
}

// ---------------- persistent-B fused FFN-up ----------------
#define PD_B1   36864
#define PD_B2   73728
#define PD_TOT  110592
#define MSTRIDE 18

__global__ void __launch_bounds__(256) hmma_dualp_kernel(
    const __nv_bfloat16* __restrict__ A,
    const __nv_bfloat16* __restrict__ B1, const float* __restrict__ b1,
    const __nv_bfloat16* __restrict__ B2, const float* __restrict__ b2,
    __nv_bfloat16* __restrict__ outp, int M, int N, int K)
{
    extern __shared__ __align__(16) char smem[];
    uint32_t sb = smem_u32(smem);
    int tid = threadIdx.x, lane = tid & 31, wid = tid >> 5;
    int n0 = blockIdx.x * 64;
    int by = blockIdx.y;
    int warp_m = (wid & 1) * 64, warp_n = (wid >> 1) * 16;

    int sub = lane >> 3, lrow = lane & 7;
    uint32_t a_off = ((warp_m + (sub & 1) * 8 + lrow) * PAD + (sub >> 1) * 8) * 2;
    uint32_t b_sub = ((warp_n + (sub >> 1) * 8 + lrow) * PAD + (sub & 1) * 8) * 2;

    const int ld4 = K >> 3;   // 32
    int lrow4 = tid >> 3, lcol4 = tid & 7;
    uint32_t sdst = sb + lrow4 * PAD2 + lcol4 * 16;

    {
        const uint4* bg1 = (const uint4*)(B1 + (size_t)n0 * K) + (size_t)lrow4 * ld4 + lcol4;
        const uint4* bg2 = (const uint4*)(B2 + (size_t)n0 * K) + (size_t)lrow4 * ld4 + lcol4;
        #pragma unroll
        for (int c = 0; c < 4; c++) {
            cp16(sdst + PD_B1 + c * 9216,             bg1 + c * 8);
            cp16(sdst + PD_B1 + c * 9216 + 32 * PAD2, bg1 + (size_t)32 * ld4 + c * 8);
            cp16(sdst + PD_B2 + c * 9216,             bg2 + c * 8);
            cp16(sdst + PD_B2 + c * 9216 + 32 * PAD2, bg2 + (size_t)32 * ld4 + c * 8);
        }
    }

    int nm = (MT128 - 1 - by) / MSTRIDE + 1;
    int G = nm * 4;

    {
        int m0 = by * 128;
        const uint4* ag = (const uint4*)(A + (size_t)m0 * K) + (size_t)lrow4 * ld4 + lcol4;
        #pragma unroll
        for (int p = 0; p < 4; p++)
            cp16(sdst + p * 32 * PAD2, ag + (size_t)p * 32 * ld4);
    }
    CP_COMMIT();

    float acc1[4][2][4], acc2[4][2][4];
    int crow = lane >> 2, ccol = (lane & 3) * 2;

    for (int g = 0; g < G; g++) {
        int c = g & 3, stg = g & 1;
        if (c == 0) {
            #pragma unroll
            for (int i = 0; i < 4; i++)
                #pragma unroll
                for (int j = 0; j < 2; j++)
                    #pragma unroll
                    for (int k = 0; k < 4; k++) { acc1[i][j][k] = 0.f; acc2[i][j][k] = 0.f; }
        }
        CP_WAIT0();
        __syncthreads();
        if (g + 1 < G) {
            int gn = g + 1, jm = gn >> 2, cn = gn & 3;
            int m0n = (by + jm * MSTRIDE) * 128;
            const uint4* ag = (const uint4*)(A + (size_t)m0n * K)
                              + (size_t)lrow4 * ld4 + lcol4 + cn * 8;
            uint32_t d = sdst + (stg ^ 1) * 18432;
            #pragma unroll
            for (int p = 0; p < 4; p++)
                cp16(d + p * 32 * PAD2, ag + (size_t)p * 32 * ld4);
            CP_COMMIT();
        }
        uint32_t ab  = sb + stg * 18432 + a_off;
        uint32_t bb1 = sb + PD_B1 + c * 9216 + b_sub;
        uint32_t bb2 = sb + PD_B2 + c * 9216 + b_sub;
        #pragma unroll
        for (int ks = 0; ks < 4; ks++) {
            uint32_t af[4][4], bf1[4], bf2[4];
            #pragma unroll
            for (int mt = 0; mt < 4; mt++) ldsm4(af[mt], ab + (mt * 16 * PAD + ks * 16) * 2);
            ldsm4(bf1, bb1 + (ks * 16) * 2);
            ldsm4(bf2, bb2 + (ks * 16) * 2);
            #pragma unroll
            for (int mt = 0; mt < 4; mt++) {
                mma_bf16(acc1[mt][0], af[mt], &bf1[0]);
                mma_bf16(acc1[mt][1], af[mt], &bf1[2]);
                mma_bf16(acc2[mt][0], af[mt], &bf2[0]);
                mma_bf16(acc2[mt][1], af[mt], &bf2[2]);
            }
        }
        if (c == 3) {
            int m0 = (by + (g >> 2) * MSTRIDE) * 128;
            #pragma unroll
            for (int mt = 0; mt < 4; mt++) {
                #pragma unroll
                for (int half = 0; half < 2; half++) {
                    int m = m0 + warp_m + mt * 16 + crow + half * 8;
                    if (m >= M) continue;
                    #pragma unroll
                    for (int nt = 0; nt < 2; nt++) {
                        int n = n0 + warp_n + nt * 8 + ccol;
                        float z0 = acc1[mt][nt][half * 2 + 0] + b1[n];
                        float z1 = acc1[mt][nt][half * 2 + 1] + b1[n + 1];
                        float g0 = acc2[mt][nt][half * 2 + 0] + b2[n];
                        float g1 = acc2[mt][nt][half * 2 + 1] + b2[n + 1];
                        float h0 = (z0 / (1.0f + __expf(-z0))) * g0;
                        float h1 = (z1 / (1.0f + __expf(-z1))) * g1;
                        *(__nv_bfloat162*)(outp + (size_t)m * N + n) = __floats2bfloat162_rn(h0, h1);
                    }
                }
            }
        }
    }
}

// ---------------- deformable-attention sampling (fp8 value) ----------------
// 32 tokens/block; warp = 4 tokens x 8 heads; one lane per head, 32 fp8 channels (2x uint4).
__global__ void __launch_bounds__(256) msda_kernel(
    const float* __restrict__ ref,
    const unsigned char* __restrict__ value,
    const __half* __restrict__ off,
    const __half* __restrict__ awl,
    __nv_bfloat16* __restrict__ outp)
{
    int tid   = threadIdx.x;
    int wid   = tid >> 5, lane = tid & 31;
    int token = blockIdx.x * 32 + wid * 4 + (lane >> 3);
    if (token >= MTOK) return;
    int h = lane & 7;

    const __half* aw = awl + (size_t)token * 128 + h * 16;
    const __half* of = off + (size_t)token * 256 + h * 32;

    float wgt[16];
    float mx = -1e30f;
    #pragma unroll
    for (int s = 0; s < 16; s++) { wgt[s] = __half2float(aw[s]); mx = fmaxf(mx, wgt[s]); }
    float sum = 0.f;
    #pragma unroll
    for (int s = 0; s < 16; s++) { wgt[s] = __expf(wgt[s] - mx); sum += wgt[s]; }
    float inv = 1.0f / sum;

    int b = (token >= LQ) ? 1 : 0;
    const uint4* vb = (const uint4*)(value + (size_t)b * LQ * 256) + h * 2;

    __half2 acch[16];
    #pragma unroll
    for (int i = 0; i < 16; i++) acch[i] = __half2(0, 0);

    #pragma unroll
    for (int l = 0; l < 4; l++) {
        const int H  = c_H[l];
        const int W  = c_W[l];
        const int st = c_st[l];
        float rx = ref[(size_t)token * 8 + l * 2 + 0];
        float ry = ref[(size_t)token * 8 + l * 2 + 1];
        #pragma unroll
        for (int p = 0; p < 4; p++) {
            int s = l * 4 + p;
            float x = fmaf(rx, (float)W, __half2float(of[s * 2 + 0]) - 0.5f);
            float y = fmaf(ry, (float)H, __half2float(of[s * 2 + 1]) - 0.5f);
            float x0f = floorf(x), y0f = floorf(y);
            int   x0  = (int)x0f,  y0  = (int)y0f;
            float lx = x - x0f, ly = y - y0f;
            float ws  = wgt[s] * inv;
            float w00 = (1.f - lx) * (1.f - ly) * ws;
            float w01 = lx * (1.f - ly) * ws;
            float w10 = (1.f - lx) * ly * ws;
            float w11 = lx * ly * ws;
            bool x0v = (x0 >= 0)     && (x0 < W);
            bool x1v = (x0 + 1 >= 0) && (x0 + 1 < W);
            #pragma unroll
            for (int dy = 0; dy < 2; dy++) {
                int yy = y0 + dy;
                if (yy < 0 || yy >= H) continue;
                long long base = (long long)(st + yy * W) * 16;   // uint4 row stride
                float wa = dy ? w10 : w00;
                float wb = dy ? w11 : w01;
                if (x0v) {
                    long long pa = base + (long long)x0 * 16;
                    uint4 v0 = vb[pa];
                    uint4 v1 = vb[pa + 1];
                    __half2 wh = __float2half2_rn(wa);
                    acc8(acch,     v0, wh);
                    acc8(acch + 8, v1, wh);
                }
                if (x1v) {
                    long long pa = base + (long long)(x0 + 1) * 16;
                    uint4 v0 = vb[pa];
                    uint4 v1 = vb[pa + 1];
                    __half2 wh = __float2half2_rn(wb);
                    acc8(acch,     v0, wh);
                    acc8(acch + 8, v1, wh);
                }
            }
        }
    }
    // 32 bf16 outputs = 4 uint4 stores
    __nv_bfloat16* op = outp + (size_t)token * 256 + h * 32;
    #pragma unroll
    for (int q = 0; q < 4; q++) {
        uint4 o;
        float2 f;
        f = __half22float2(acch[q*4+0]); *(__nv_bfloat162*)&o.x = __floats2bfloat162_rn(f.x, f.y);
        f = __half22float2(acch[q*4+1]); *(__nv_bfloat162*)&o.y = __floats2bfloat162_rn(f.x, f.y);
        f = __half22float2(acch[q*4+2]); *(__nv_bfloat162*)&o.z = __floats2bfloat162_rn(f.x, f.y);
        f = __half22float2(acch[q*4+3]); *(__nv_bfloat162*)&o.w = __floats2bfloat162_rn(f.x, f.y);
        *(uint4*)(op + q * 8) = o;
    }
}

// ---------------- host launch ----------------
template <typename T>
static T* symaddr(const void* sym) {
    void* p = nullptr;
    cudaGetSymbolAddress(&p, sym);
    return (T*)p;
}

extern "C" void kernel_launch(void* const* d_in, const int* in_sizes, int n_in,
                              void* d_out, int out_size) {
    (void)in_sizes; (void)n_in; (void)out_size;
    const float* query = (const float*)d_in[0];
    const float* qpos  = (const float*)d_in[1];
    const float* ref   = (const float*)d_in[2];
    const float* nw1   = (const float*)d_in[5];
    const float* Wv    = (const float*)d_in[6];
    const float* bv    = (const float*)d_in[7];
    const float* Woff  = (const float*)d_in[8];
    const float* boff  = (const float*)d_in[9];
    const float* Waw   = (const float*)d_in[10];
    const float* baw   = (const float*)d_in[11];
    const float* Wo    = (const float*)d_in[12];
    const float* bo    = (const float*)d_in[13];
    const float* lsa   = (const float*)d_in[14];
    const float* nw2   = (const float*)d_in[15];
    const float* W1    = (const float*)d_in[16];
    const float* b1    = (const float*)d_in[17];
    const float* W2    = (const float*)d_in[18];
    const float* b2    = (const float*)d_in[19];
    const float* W3    = (const float*)d_in[20];
    const float* b3    = (const float*)d_in[21];
    const float* lsf   = (const float*)d_in[22];
    float* out = (float*)d_out;

    __nv_bfloat16* nb    = symaddr<__nv_bfloat16>(g_nb);
    __nv_bfloat16* qb    = symaddr<__nv_bfloat16>(g_qb);
    unsigned char* val8  = symaddr<unsigned char>(g_value8);
    __half*        poff  = symaddr<__half>(g_off);
    __half*        pawl  = symaddr<__half>(g_awl);
    __nv_bfloat16* attnb = symaddr<__nv_bfloat16>(g_attnb);
    float*         px    = symaddr<float>(g_x);
    __nv_bfloat16* n2b   = symaddr<__nv_bfloat16>(g_n2b);
    __nv_bfloat16* hb    = symaddr<__nv_bfloat16>(g_hb);
    __nv_bfloat16* wb    = symaddr<__nv_bfloat16>(g_wb);

    const int GSM = NSTAGE * STAGE_BYTES;   // 110592
    cudaFuncSetAttribute(hmma_gemm_kernel,  cudaFuncAttributeMaxDynamicSharedMemorySize, GSM);
    cudaFuncSetAttribute(hmma_dualp_kernel, cudaFuncAttributeMaxDynamicSharedMemorySize, PD_TOT);

    // 0. weights -> bf16
    WSrc ws; ws.s[0] = Wv; ws.s[1] = Woff; ws.s[2] = Waw; ws.s[3] = Wo;
    ws.s[4] = W1; ws.s[5] = W2; ws.s[6] = W3;
    wconv_kernel<<<dim3(256, 7), 256>>>(ws);

    // 1. rmsnorm -> normed bf16, q = normed+pos bf16
    rmsnorm_kernel<<<(MTOK + 7) / 8, 256>>>(query, nw1, nb, qpos, qb);
    // 2. value = normed @ Wv^T + bv (fp8 out)
    hmma_gemm_kernel<<<dim3(2, MT128), 256, GSM>>>(nb, wb + WOFF_WV, bv, nullptr,
        nullptr, nullptr, val8, MTOK, 256, 256, 256, nullptr, nullptr);
    // 3. fused offsets+logits: q @ [Woff;Waw]^T, split fp16 outputs
    hmma_gemm_kernel<<<dim3(3, MT128), 256, GSM>>>(qb, wb + WOFF_WOFF, boff, baw,
        (float*)poff, (float*)pawl, nullptr, MTOK, 384, 256, 256, nullptr, nullptr);
    // 4. deformable sampling -> attn bf16 (lane/head, 32ch fp8)
    msda_kernel<<<(MTOK + 31) / 32, 256>>>(ref, val8, poff, pawl, attnb);
    // 5. x = query + ls_attn * (attn @ Wo^T + bo)
    hmma_gemm_kernel<<<dim3(2, MT128), 256, GSM>>>(attnb, wb + WOFF_WO, bo, nullptr,
        px, nullptr, nullptr, MTOK, 256, 256, 256, query, lsa);
    // 6. n2 = rmsnorm(x) bf16
    rmsnorm_kernel<<<(MTOK + 7) / 8, 256>>>(px, nw2, n2b, nullptr, nullptr);
    // 7. FFN-up persistent-B
    hmma_dualp_kernel<<<dim3(16, MSTRIDE), 256, PD_TOT>>>(n2b, wb + WOFF_W1, b1,
        wb + WOFF_W2, b2, hb, MTOK, DFFN, 256);
    // 8. out = x + ls_ffn * (h @ W3^T + b3)
    hmma_gemm_kernel<<<dim3(2, MT128), 256, GSM>>>(hb, wb + WOFF_W3, b3, nullptr,
        out, nullptr, nullptr, MTOK, 256, 256, 1024, px, lsf);
}

// round 16
// speedup vs baseline: 1.0558x; 1.0558x over previous
#include <cuda_runtime.h>
#include <cuda_bf16.h>
#include <cuda_fp16.h>
#include <cuda_fp8.h>
#include <cstdint>
#include <math.h>

// ---------------- problem constants ----------------
#define BSZ   2
#define LQ    17821
#define CDIM  256
#define MTOK  (BSZ*LQ)          // 35642
#define MPAD  35712             // 279 * 128
#define MT128 279
#define DFFN  1024
#define PAD   72                // smem row stride in halves (144B, conflict-free)
#define PAD2  (PAD*2)

__device__ __constant__ int c_H[4]  = {100, 50, 25, 13};
__device__ __constant__ int c_W[4]  = {134, 67, 34, 17};
__device__ __constant__ int c_st[4] = {0, 13400, 16750, 17600};

// ---------------- scratch (no allocs; zero-initialized .bss) ----------------
__device__ __nv_bfloat16 g_nb    [(size_t)MPAD*CDIM];
__device__ __nv_bfloat16 g_qb    [(size_t)MPAD*CDIM];
__device__ unsigned char g_value8[(size_t)MPAD*CDIM];   // fp8 e4m3 value tensor
__device__ __half        g_off   [(size_t)MTOK*CDIM];
__device__ __half        g_awl   [(size_t)MTOK*128];
__device__ __nv_bfloat16 g_attnb [(size_t)MPAD*CDIM];
__device__ float         g_x     [(size_t)MTOK*CDIM];
__device__ __nv_bfloat16 g_n2b   [(size_t)MPAD*CDIM];
__device__ __nv_bfloat16 g_hb    [(size_t)MPAD*DFFN];
// converted weights: Wv,Woff,Waw,Wo,W1,W2,W3
#define WOFF_WV   0
#define WOFF_WOFF 65536
#define WOFF_WAW  131072
#define WOFF_WO   163840
#define WOFF_W1   229376
#define WOFF_W2   491520
#define WOFF_W3   753664
__device__ __nv_bfloat16 g_wb[1015808];

// ================= helpers =================
__device__ __forceinline__ uint32_t smem_u32(const void* p) {
    uint32_t a;
    asm("{ .reg .u64 t; cvta.to.shared.u64 t, %1; cvt.u32.u64 %0, t; }" : "=r"(a) : "l"(p));
    return a;
}
__device__ __forceinline__ void ldsm4(uint32_t* r, uint32_t addr) {
    asm volatile("ldmatrix.sync.aligned.m8n8.x4.shared.b16 {%0,%1,%2,%3}, [%4];"
        : "=r"(r[0]), "=r"(r[1]), "=r"(r[2]), "=r"(r[3]) : "r"(addr));
}
__device__ __forceinline__ void mma_bf16(float* c, const uint32_t* a, const uint32_t* b) {
    asm volatile(
        "mma.sync.aligned.m16n8k16.row.col.f32.bf16.bf16.f32 "
        "{%0,%1,%2,%3}, {%4,%5,%6,%7}, {%8,%9}, {%0,%1,%2,%3};"
        : "+f"(c[0]), "+f"(c[1]), "+f"(c[2]), "+f"(c[3])
        : "r"(a[0]), "r"(a[1]), "r"(a[2]), "r"(a[3]), "r"(b[0]), "r"(b[1]));
}
__device__ __forceinline__ void cp16(uint32_t dst, const void* src) {
    asm volatile("cp.async.ca.shared.global [%0], [%1], 16;" :: "r"(dst), "l"(src));
}
#define CP_COMMIT() asm volatile("cp.async.commit_group;" ::: "memory")
#define CP_WAIT1()  asm volatile("cp.async.wait_group 1;" ::: "memory")
#define CP_WAIT0()  asm volatile("cp.async.wait_group 0;" ::: "memory")

__device__ __forceinline__ __half2 fp8x2_to_h2(unsigned short s) {
    __half2_raw r = __nv_cvt_fp8x2_to_halfraw2((__nv_fp8x2_storage_t)s, __NV_E4M3);
    return *(__half2*)&r;
}
__device__ __forceinline__ void acc8(__half2* acch, uint4 v, __half2 wh) {
    acch[0] = __hfma2(fp8x2_to_h2(v.x & 0xFFFFu), wh, acch[0]);
    acch[1] = __hfma2(fp8x2_to_h2(v.x >> 16),     wh, acch[1]);
    acch[2] = __hfma2(fp8x2_to_h2(v.y & 0xFFFFu), wh, acch[2]);
    acch[3] = __hfma2(fp8x2_to_h2(v.y >> 16),     wh, acch[3]);
    acch[4] = __hfma2(fp8x2_to_h2(v.z & 0xFFFFu), wh, acch[4]);
    acch[5] = __hfma2(fp8x2_to_h2(v.z >> 16),     wh, acch[5]);
    acch[6] = __hfma2(fp8x2_to_h2(v.w & 0xFFFFu), wh, acch[6]);
    acch[7] = __hfma2(fp8x2_to_h2(v.w >> 16),     wh, acch[7]);
}

// ---------------- weight fp32 -> bf16 convert ----------------
struct WSrc { const float* s[7]; };
__device__ __constant__ int c_wsz [7] = {65536, 65536, 32768, 65536, 262144, 262144, 262144};
__device__ __constant__ int c_woff[7] = {WOFF_WV, WOFF_WOFF, WOFF_WAW, WOFF_WO, WOFF_W1, WOFF_W2, WOFF_W3};

__global__ void __launch_bounds__(256) wconv_kernel(WSrc w) {
    int seg = blockIdx.y;
    int i = (blockIdx.x * 256 + threadIdx.x) * 4;
    if (i >= c_wsz[seg]) return;
    float4 v = *(const float4*)(w.s[seg] + i);
    __nv_bfloat16* d = g_wb + c_woff[seg] + i;
    *(__nv_bfloat162*)(d)     = __floats2bfloat162_rn(v.x, v.y);
    *(__nv_bfloat162*)(d + 2) = __floats2bfloat162_rn(v.z, v.w);
}

// ---------------- RMSNorm -> bf16 (+ optional bf16 normed+addend) ----------------
__global__ void __launch_bounds__(256) rmsnorm_kernel(
    const float* __restrict__ x, const float* __restrict__ w,
    __nv_bfloat16* __restrict__ out, const float* __restrict__ addend,
    __nv_bfloat16* __restrict__ out2)
{
    int row  = blockIdx.x * 8 + (threadIdx.x >> 5);
    if (row >= MTOK) return;
    int lane = threadIdx.x & 31;
    const float4* xr = (const float4*)(x + (size_t)row * CDIM);
    float4 v0 = xr[lane];
    float4 v1 = xr[lane + 32];
    float ss = v0.x*v0.x + v0.y*v0.y + v0.z*v0.z + v0.w*v0.w
             + v1.x*v1.x + v1.y*v1.y + v1.z*v1.z + v1.w*v1.w;
    #pragma unroll
    for (int o = 16; o > 0; o >>= 1) ss += __shfl_xor_sync(0xffffffffu, ss, o);
    float s = rsqrtf(ss * (1.0f / CDIM) + 1e-6f);
    const float4* w4 = (const float4*)w;
    float4 g0 = w4[lane], g1 = w4[lane + 32];
    float n0x = v0.x*s*g0.x, n0y = v0.y*s*g0.y, n0z = v0.z*s*g0.z, n0w = v0.w*s*g0.w;
    float n1x = v1.x*s*g1.x, n1y = v1.y*s*g1.y, n1z = v1.z*s*g1.z, n1w = v1.w*s*g1.w;
    __nv_bfloat162* o2 = (__nv_bfloat162*)(out + (size_t)row * CDIM);
    o2[lane*2+0]  = __floats2bfloat162_rn(n0x, n0y);
    o2[lane*2+1]  = __floats2bfloat162_rn(n0z, n0w);
    o2[64+lane*2] = __floats2bfloat162_rn(n1x, n1y);
    o2[65+lane*2] = __floats2bfloat162_rn(n1z, n1w);
    if (out2) {
        const float4* a4 = (const float4*)(addend + (size_t)row * CDIM);
        float4 p0 = a4[lane], p1 = a4[lane + 32];
        __nv_bfloat162* q2 = (__nv_bfloat162*)(out2 + (size_t)row * CDIM);
        q2[lane*2+0]  = __floats2bfloat162_rn(n0x + p0.x, n0y + p0.y);
        q2[lane*2+1]  = __floats2bfloat162_rn(n0z + p0.z, n0w + p0.w);
        q2[64+lane*2] = __floats2bfloat162_rn(n1x + p1.x, n1y + p1.y);
        q2[65+lane*2] = __floats2bfloat162_rn(n1z + p1.z, n1w + p1.w);
    }
}

// ---------------- HMMA GEMM, 3-stage cp.async ring (R10 config) ----------------
#define TILE_BYTES  (128 * PAD * 2)     // 18432
#define STAGE_BYTES (2 * TILE_BYTES)    // 36864: [As | Bs]
#define NSTAGE 3

__global__ void __launch_bounds__(256) hmma_gemm_kernel(
    const __nv_bfloat16* __restrict__ A, const __nv_bfloat16* __restrict__ B,
    const float* __restrict__ bias, const float* __restrict__ bias2,
    float* __restrict__ outp, float* __restrict__ outp2,
    unsigned char* __restrict__ out8,
    int M, int N, int N1, int K,
    const float* __restrict__ residual, const float* __restrict__ gain)
{
    extern __shared__ __align__(16) char smem[];
    uint32_t sb = smem_u32(smem);
    int tid = threadIdx.x, lane = tid & 31, wid = tid >> 5;
    int m0 = blockIdx.y * 128, n0 = blockIdx.x * 128;
    int warp_m = (wid & 1) * 64, warp_n = (wid >> 1) * 32;

    float acc[4][4][4] = {};

    int sub = lane >> 3, lrow = lane & 7;
    uint32_t a_off = ((warp_m + (sub & 1) * 8 + lrow) * PAD + (sub >> 1) * 8) * 2;
    uint32_t b_off = TILE_BYTES + ((warp_n + (sub >> 1) * 8 + lrow) * PAD + (sub & 1) * 8) * 2;

    const int NCH = K >> 6;
    const int ld4 = K >> 3;
    int lrow4 = tid >> 3, lcol4 = tid & 7;
    const uint4* agl = (const uint4*)(A + (size_t)m0 * K) + (size_t)lrow4 * ld4 + lcol4;
    const uint4* bgl = (const uint4*)(B + (size_t)n0 * K) + (size_t)lrow4 * ld4 + lcol4;
    uint32_t sdst = sb + lrow4 * (PAD * 2) + lcol4 * 16;

    #pragma unroll
    for (int s = 0; s < 2; s++) {
        if (s < NCH) {
            uint32_t d = sdst + s * STAGE_BYTES;
            const uint4* ag = agl + (size_t)s * 8;
            const uint4* bg = bgl + (size_t)s * 8;
            #pragma unroll
            for (int p = 0; p < 4; p++) {
                cp16(d + p * 32 * (PAD * 2),              ag + (size_t)p * 32 * ld4);
                cp16(d + TILE_BYTES + p * 32 * (PAD * 2), bg + (size_t)p * 32 * ld4);
            }
        }
        CP_COMMIT();
    }

    int stage = 0, lstage = 2;
    for (int c = 0; c < NCH; c++) {
        if (c + 1 < NCH) CP_WAIT1(); else CP_WAIT0();
        __syncthreads();
        if (c + 2 < NCH) {
            uint32_t d = sdst + lstage * STAGE_BYTES;
            const uint4* ag = agl + (size_t)(c + 2) * 8;
            const uint4* bg = bgl + (size_t)(c + 2) * 8;
            #pragma unroll
            for (int p = 0; p < 4; p++) {
                cp16(d + p * 32 * (PAD * 2),              ag + (size_t)p * 32 * ld4);
                cp16(d + TILE_BYTES + p * 32 * (PAD * 2), bg + (size_t)p * 32 * ld4);
            }
            CP_COMMIT();
            if (++lstage == NSTAGE) lstage = 0;
        }
        uint32_t ab = sb + stage * STAGE_BYTES + a_off;
        uint32_t bb = sb + stage * STAGE_BYTES + b_off;
        #pragma unroll
        for (int ks = 0; ks < 4; ks++) {
            uint32_t af[4][4], bf[2][4];
            #pragma unroll
            for (int mt = 0; mt < 4; mt++) ldsm4(af[mt], ab + (mt * 16 * PAD + ks * 16) * 2);
            #pragma unroll
            for (int pr = 0; pr < 2; pr++) ldsm4(bf[pr], bb + (pr * 16 * PAD + ks * 16) * 2);
            #pragma unroll
            for (int mt = 0; mt < 4; mt++) {
                mma_bf16(acc[mt][0], af[mt], &bf[0][0]);
                mma_bf16(acc[mt][1], af[mt], &bf[0][2]);
                mma_bf16(acc[mt][2], af[mt], &bf[1][0]);
                mma_bf16(acc[mt][3], af[mt], &bf[1][2]);
            }
        }
        if (++stage == NSTAGE) stage = 0;
    }

    int crow = lane >> 2, ccol = (lane & 3) * 2;
    #pragma unroll
    for (int mt = 0; mt < 4; mt++) {
        #pragma unroll
        for (int half = 0; half < 2; half++) {
            int m = m0 + warp_m + mt * 16 + crow + half * 8;
            if (m >= M) continue;
            #pragma unroll
            for (int nt = 0; nt < 4; nt++) {
                int n = n0 + warp_n + nt * 8 + ccol;
                float vx = acc[mt][nt][half * 2 + 0];
                float vy = acc[mt][nt][half * 2 + 1];
                if (outp2) {
                    if (n < N1) {
                        float2 bs = *(const float2*)(bias + n);
                        __half2 hv = __floats2half2_rn(vx + bs.x, vy + bs.y);
                        *(__half2*)((__half*)outp + (size_t)m * N1 + n) = hv;
                    } else {
                        int S2 = N - N1, n2 = n - N1;
                        float2 bs = *(const float2*)(bias2 + n2);
                        __half2 hv = __floats2half2_rn(vx + bs.x, vy + bs.y);
                        *(__half2*)((__half*)outp2 + (size_t)m * S2 + n2) = hv;
                    }
                } else {
                    float2 bs = *(const float2*)(bias + n);
                    vx += bs.x; vy += bs.y;
                    if (residual) {
                        float2 rr = *(const float2*)(residual + (size_t)m * N1 + n);
                        float2 gg = *(const float2*)(gain + n);
                        vx = rr.x + gg.x * vx;
                        vy = rr.y + gg.y * vy;
                    }
                    if (out8) {
                        *(unsigned short*)(out8 + (size_t)m * N1 + n) =
                            (unsigned short)__nv_cvt_float2_to_fp8x2(
                                make_float2(vx, vy), __NV_SATFINITE, __NV_E4M3);
                    } else {
                        *(float2*)(outp + (size_t)m * N1 + n) = make_float2(vx, vy);
                    }
                }
            }
        }
    }
}

// ---------------- persistent-B fused FFN-up ----------------
#define PD_B1   36864
#define PD_B2   73728
#define PD_TOT  110592
#define MSTRIDE 18

__global__ void __launch_bounds__(256) hmma_dualp_kernel(
    const __nv_bfloat16* __restrict__ A,
    const __nv_bfloat16* __restrict__ B1, const float* __restrict__ b1,
    const __nv_bfloat16* __restrict__ B2, const float* __restrict__ b2,
    __nv_bfloat16* __restrict__ outp, int M, int N, int K)
{
    extern __shared__ __align__(16) char smem[];
    uint32_t sb = smem_u32(smem);
    int tid = threadIdx.x, lane = tid & 31, wid = tid >> 5;
    int n0 = blockIdx.x * 64;
    int by = blockIdx.y;
    int warp_m = (wid & 1) * 64, warp_n = (wid >> 1) * 16;

    int sub = lane >> 3, lrow = lane & 7;
    uint32_t a_off = ((warp_m + (sub & 1) * 8 + lrow) * PAD + (sub >> 1) * 8) * 2;
    uint32_t b_sub = ((warp_n + (sub >> 1) * 8 + lrow) * PAD + (sub & 1) * 8) * 2;

    const int ld4 = K >> 3;   // 32
    int lrow4 = tid >> 3, lcol4 = tid & 7;
    uint32_t sdst = sb + lrow4 * PAD2 + lcol4 * 16;

    {
        const uint4* bg1 = (const uint4*)(B1 + (size_t)n0 * K) + (size_t)lrow4 * ld4 + lcol4;
        const uint4* bg2 = (const uint4*)(B2 + (size_t)n0 * K) + (size_t)lrow4 * ld4 + lcol4;
        #pragma unroll
        for (int c = 0; c < 4; c++) {
            cp16(sdst + PD_B1 + c * 9216,             bg1 + c * 8);
            cp16(sdst + PD_B1 + c * 9216 + 32 * PAD2, bg1 + (size_t)32 * ld4 + c * 8);
            cp16(sdst + PD_B2 + c * 9216,             bg2 + c * 8);
            cp16(sdst + PD_B2 + c * 9216 + 32 * PAD2, bg2 + (size_t)32 * ld4 + c * 8);
        }
    }

    int nm = (MT128 - 1 - by) / MSTRIDE + 1;
    int G = nm * 4;

    {
        int m0 = by * 128;
        const uint4* ag = (const uint4*)(A + (size_t)m0 * K) + (size_t)lrow4 * ld4 + lcol4;
        #pragma unroll
        for (int p = 0; p < 4; p++)
            cp16(sdst + p * 32 * PAD2, ag + (size_t)p * 32 * ld4);
    }
    CP_COMMIT();

    float acc1[4][2][4], acc2[4][2][4];
    int crow = lane >> 2, ccol = (lane & 3) * 2;

    for (int g = 0; g < G; g++) {
        int c = g & 3, stg = g & 1;
        if (c == 0) {
            #pragma unroll
            for (int i = 0; i < 4; i++)
                #pragma unroll
                for (int j = 0; j < 2; j++)
                    #pragma unroll
                    for (int k = 0; k < 4; k++) { acc1[i][j][k] = 0.f; acc2[i][j][k] = 0.f; }
        }
        CP_WAIT0();
        __syncthreads();
        if (g + 1 < G) {
            int gn = g + 1, jm = gn >> 2, cn = gn & 3;
            int m0n = (by + jm * MSTRIDE) * 128;
            const uint4* ag = (const uint4*)(A + (size_t)m0n * K)
                              + (size_t)lrow4 * ld4 + lcol4 + cn * 8;
            uint32_t d = sdst + (stg ^ 1) * 18432;
            #pragma unroll
            for (int p = 0; p < 4; p++)
                cp16(d + p * 32 * PAD2, ag + (size_t)p * 32 * ld4);
            CP_COMMIT();
        }
        uint32_t ab  = sb + stg * 18432 + a_off;
        uint32_t bb1 = sb + PD_B1 + c * 9216 + b_sub;
        uint32_t bb2 = sb + PD_B2 + c * 9216 + b_sub;
        #pragma unroll
        for (int ks = 0; ks < 4; ks++) {
            uint32_t af[4][4], bf1[4], bf2[4];
            #pragma unroll
            for (int mt = 0; mt < 4; mt++) ldsm4(af[mt], ab + (mt * 16 * PAD + ks * 16) * 2);
            ldsm4(bf1, bb1 + (ks * 16) * 2);
            ldsm4(bf2, bb2 + (ks * 16) * 2);
            #pragma unroll
            for (int mt = 0; mt < 4; mt++) {
                mma_bf16(acc1[mt][0], af[mt], &bf1[0]);
                mma_bf16(acc1[mt][1], af[mt], &bf1[2]);
                mma_bf16(acc2[mt][0], af[mt], &bf2[0]);
                mma_bf16(acc2[mt][1], af[mt], &bf2[2]);
            }
        }
        if (c == 3) {
            int m0 = (by + (g >> 2) * MSTRIDE) * 128;
            #pragma unroll
            for (int mt = 0; mt < 4; mt++) {
                #pragma unroll
                for (int half = 0; half < 2; half++) {
                    int m = m0 + warp_m + mt * 16 + crow + half * 8;
                    if (m >= M) continue;
                    #pragma unroll
                    for (int nt = 0; nt < 2; nt++) {
                        int n = n0 + warp_n + nt * 8 + ccol;
                        float2 bb1v = *(const float2*)(b1 + n);
                        float2 bb2v = *(const float2*)(b2 + n);
                        float z0 = acc1[mt][nt][half * 2 + 0] + bb1v.x;
                        float z1 = acc1[mt][nt][half * 2 + 1] + bb1v.y;
                        float g0 = acc2[mt][nt][half * 2 + 0] + bb2v.x;
                        float g1 = acc2[mt][nt][half * 2 + 1] + bb2v.y;
                        float h0 = (z0 / (1.0f + __expf(-z0))) * g0;
                        float h1 = (z1 / (1.0f + __expf(-z1))) * g1;
                        *(__nv_bfloat162*)(outp + (size_t)m * N + n) = __floats2bfloat162_rn(h0, h1);
                    }
                }
            }
        }
    }
}

// ---------------- deformable-attention sampling (fp8 value) ----------------
// 16 tokens/block; half-warp per token: 8 heads x 2 lanes, each lane 16 fp8 channels (uint4).
__global__ void __launch_bounds__(256) msda_kernel(
    const float* __restrict__ ref,
    const unsigned char* __restrict__ value,
    const __half* __restrict__ off,
    const __half* __restrict__ awl,
    __nv_bfloat16* __restrict__ outp)
{
    int tid   = threadIdx.x;
    int wid   = tid >> 5, lane = tid & 31;
    int token = blockIdx.x * 16 + wid * 2 + (lane >> 4);
    if (token >= MTOK) return;
    int h  = (lane >> 1) & 7;
    int cg = lane & 1;

    const __half* aw = awl + (size_t)token * 128 + h * 16;
    const __half* of = off + (size_t)token * 256 + h * 32;

    float wgt[16];
    float mx = -1e30f;
    #pragma unroll
    for (int s = 0; s < 16; s++) { wgt[s] = __half2float(aw[s]); mx = fmaxf(mx, wgt[s]); }
    float sum = 0.f;
    #pragma unroll
    for (int s = 0; s < 16; s++) { wgt[s] = __expf(wgt[s] - mx); sum += wgt[s]; }
    float inv = 1.0f / sum;

    int b = (token >= LQ) ? 1 : 0;
    const uint4* vb = (const uint4*)(value + (size_t)b * LQ * 256) + h * 2 + cg;

    __half2 acch[8] = {__half2(0,0), __half2(0,0), __half2(0,0), __half2(0,0),
                       __half2(0,0), __half2(0,0), __half2(0,0), __half2(0,0)};
    #pragma unroll
    for (int l = 0; l < 4; l++) {
        const int H  = c_H[l];
        const int W  = c_W[l];
        const int st = c_st[l];
        float rx = ref[(size_t)token * 8 + l * 2 + 0];
        float ry = ref[(size_t)token * 8 + l * 2 + 1];
        #pragma unroll
        for (int p = 0; p < 4; p++) {
            int s = l * 4 + p;
            float x = fmaf(rx, (float)W, __half2float(of[s * 2 + 0]) - 0.5f);
            float y = fmaf(ry, (float)H, __half2float(of[s * 2 + 1]) - 0.5f);
            float x0f = floorf(x), y0f = floorf(y);
            int   x0  = (int)x0f,  y0  = (int)y0f;
            float lx = x - x0f, ly = y - y0f;
            float ws  = wgt[s] * inv;
            float w00 = (1.f - lx) * (1.f - ly) * ws;
            float w01 = lx * (1.f - ly) * ws;
            float w10 = (1.f - lx) * ly * ws;
            float w11 = lx * ly * ws;
            bool x0v = (x0 >= 0)     && (x0 < W);
            bool x1v = (x0 + 1 >= 0) && (x0 + 1 < W);
            #pragma unroll
            for (int dy = 0; dy < 2; dy++) {
                int yy = y0 + dy;
                if (yy < 0 || yy >= H) continue;
                long long base = (long long)(st + yy * W) * 16;
                float wa = dy ? w10 : w00;
                float wb = dy ? w11 : w01;
                if (x0v) {
                    uint4 v = vb[base + (long long)x0 * 16];
                    acc8(acch, v, __float2half2_rn(wa));
                }
                if (x1v) {
                    uint4 v = vb[base + (long long)(x0 + 1) * 16];
                    acc8(acch, v, __float2half2_rn(wb));
                }
            }
        }
    }
    uint4 o0, o1;
    float2 f;
    f = __half22float2(acch[0]); *(__nv_bfloat162*)&o0.x = __floats2bfloat162_rn(f.x, f.y);
    f = __half22float2(acch[1]); *(__nv_bfloat162*)&o0.y = __floats2bfloat162_rn(f.x, f.y);
    f = __half22float2(acch[2]); *(__nv_bfloat162*)&o0.z = __floats2bfloat162_rn(f.x, f.y);
    f = __half22float2(acch[3]); *(__nv_bfloat162*)&o0.w = __floats2bfloat162_rn(f.x, f.y);
    f = __half22float2(acch[4]); *(__nv_bfloat162*)&o1.x = __floats2bfloat162_rn(f.x, f.y);
    f = __half22float2(acch[5]); *(__nv_bfloat162*)&o1.y = __floats2bfloat162_rn(f.x, f.y);
    f = __half22float2(acch[6]); *(__nv_bfloat162*)&o1.z = __floats2bfloat162_rn(f.x, f.y);
    f = __half22float2(acch[7]); *(__nv_bfloat162*)&o1.w = __floats2bfloat162_rn(f.x, f.y);
    __nv_bfloat16* op = outp + (size_t)token * 256 + h * 32 + cg * 16;
    *(uint4*)(op)     = o0;
    *(uint4*)(op + 8) = o1;
}

// ---------------- host launch ----------------
template <typename T>
static T* symaddr(const void* sym) {
    void* p = nullptr;
    cudaGetSymbolAddress(&p, sym);
    return (T*)p;
}

extern "C" void kernel_launch(void* const* d_in, const int* in_sizes, int n_in,
                              void* d_out, int out_size) {
    (void)in_sizes; (void)n_in; (void)out_size;
    const float* query = (const float*)d_in[0];
    const float* qpos  = (const float*)d_in[1];
    const float* ref   = (const float*)d_in[2];
    const float* nw1   = (const float*)d_in[5];
    const float* Wv    = (const float*)d_in[6];
    const float* bv    = (const float*)d_in[7];
    const float* Woff  = (const float*)d_in[8];
    const float* boff  = (const float*)d_in[9];
    const float* Waw   = (const float*)d_in[10];
    const float* baw   = (const float*)d_in[11];
    const float* Wo    = (const float*)d_in[12];
    const float* bo    = (const float*)d_in[13];
    const float* lsa   = (const float*)d_in[14];
    const float* nw2   = (const float*)d_in[15];
    const float* W1    = (const float*)d_in[16];
    const float* b1    = (const float*)d_in[17];
    const float* W2    = (const float*)d_in[18];
    const float* b2    = (const float*)d_in[19];
    const float* W3    = (const float*)d_in[20];
    const float* b3    = (const float*)d_in[21];
    const float* lsf   = (const float*)d_in[22];
    float* out = (float*)d_out;

    __nv_bfloat16* nb    = symaddr<__nv_bfloat16>(g_nb);
    __nv_bfloat16* qb    = symaddr<__nv_bfloat16>(g_qb);
    unsigned char* val8  = symaddr<unsigned char>(g_value8);
    __half*        poff  = symaddr<__half>(g_off);
    __half*        pawl  = symaddr<__half>(g_awl);
    __nv_bfloat16* attnb = symaddr<__nv_bfloat16>(g_attnb);
    float*         px    = symaddr<float>(g_x);
    __nv_bfloat16* n2b   = symaddr<__nv_bfloat16>(g_n2b);
    __nv_bfloat16* hb    = symaddr<__nv_bfloat16>(g_hb);
    __nv_bfloat16* wb    = symaddr<__nv_bfloat16>(g_wb);

    const int GSM = NSTAGE * STAGE_BYTES;   // 110592
    cudaFuncSetAttribute(hmma_gemm_kernel,  cudaFuncAttributeMaxDynamicSharedMemorySize, GSM);
    cudaFuncSetAttribute(hmma_dualp_kernel, cudaFuncAttributeMaxDynamicSharedMemorySize, PD_TOT);

    // 0. weights -> bf16
    WSrc ws; ws.s[0] = Wv; ws.s[1] = Woff; ws.s[2] = Waw; ws.s[3] = Wo;
    ws.s[4] = W1; ws.s[5] = W2; ws.s[6] = W3;
    wconv_kernel<<<dim3(256, 7), 256>>>(ws);

    // 1. rmsnorm -> normed bf16, q = normed+pos bf16
    rmsnorm_kernel<<<(MTOK + 7) / 8, 256>>>(query, nw1, nb, qpos, qb);
    // 2. value = normed @ Wv^T + bv (fp8 out)
    hmma_gemm_kernel<<<dim3(2, MT128), 256, GSM>>>(nb, wb + WOFF_WV, bv, nullptr,
        nullptr, nullptr, val8, MTOK, 256, 256, 256, nullptr, nullptr);
    // 3. fused offsets+logits: q @ [Woff;Waw]^T, split fp16 outputs
    hmma_gemm_kernel<<<dim3(3, MT128), 256, GSM>>>(qb, wb + WOFF_WOFF, boff, baw,
        (float*)poff, (float*)pawl, nullptr, MTOK, 384, 256, 256, nullptr, nullptr);
    // 4. deformable sampling -> attn bf16 (half-warp/token, fp8 uint4 gathers)
    msda_kernel<<<(MTOK + 15) / 16, 256>>>(ref, val8, poff, pawl, attnb);
    // 5. x = query + ls_attn * (attn @ Wo^T + bo)
    hmma_gemm_kernel<<<dim3(2, MT128), 256, GSM>>>(attnb, wb + WOFF_WO, bo, nullptr,
        px, nullptr, nullptr, MTOK, 256, 256, 256, query, lsa);
    // 6. n2 = rmsnorm(x) bf16
    rmsnorm_kernel<<<(MTOK + 7) / 8, 256>>>(px, nw2, n2b, nullptr, nullptr);
    // 7. FFN-up persistent-B
    hmma_dualp_kernel<<<dim3(16, MSTRIDE), 256, PD_TOT>>>(n2b, wb + WOFF_W1, b1,
        wb + WOFF_W2, b2, hb, MTOK, DFFN, 256);
    // 8. out = x + ls_ffn * (h @ W3^T + b3)
    hmma_gemm_kernel<<<dim3(2, MT128), 256, GSM>>>(hb, wb + WOFF_W3, b3, nullptr,
        out, nullptr, nullptr, MTOK, 256, 256, 1024, px, lsf);
}